// round 1
// baseline (speedup 1.0000x reference)
#include <cuda_runtime.h>
#include <math.h>

// WeightedGaussianPool: O[i,b] = sum_j cos(pi/2 * d_ij) * step(1 - d_ij) * f_j
//                                      * exp(-beta * (d_ij - means[b])^2)
// d_ij = ||coords_i - coords_j|| / CUTOFF,  N=2048, B=64.
//
// Layout: each warp owns one (i, j-partition). Lane l owns basis l and l+32
// (accumulators in registers). Per pair (i,j): d,w are computed SIMD over a
// 32-j chunk, then broadcast lane-by-lane via shfl; the 64-wide Gaussian
// expansion is 2 EX2 warp-instructions (tails underflow to exactly 0, which
// matches the reference). Masked-out pairs are skipped via ballot compaction.

#define CUTOFF   5.0f
#define PI_HALF  1.5707963267948966f
#define NBASIS   64
#define SPLIT_J  4          // j-partitions per row i (parallelism knob)

__global__ void wgp_zero_kernel(float* __restrict__ out, int n) {
    int idx = blockIdx.x * blockDim.x + threadIdx.x;
    if (idx < n) out[idx] = 0.0f;
}

__global__ __launch_bounds__(256)
void wgp_main_kernel(const float* __restrict__ f,
                     const float* __restrict__ coords,
                     const float* __restrict__ means,
                     const float* __restrict__ beta_p,
                     float* __restrict__ out,
                     int N) {
    const int lane   = threadIdx.x & 31;
    const int warp   = threadIdx.x >> 5;
    const int gwarp  = blockIdx.x * (blockDim.x >> 5) + warp;
    const int i      = gwarp / SPLIT_J;
    const int part   = gwarp % SPLIT_J;
    if (i >= N) return;

    const float beta  = *beta_p;
    const float m1    = means[lane];
    const float m2    = means[lane + 32];
    const float inv_c = 1.0f / CUTOFF;

    // row-i coordinates (normalized)
    const float xi = coords[3 * i + 0] * inv_c;
    const float yi = coords[3 * i + 1] * inv_c;
    const float zi = coords[3 * i + 2] * inv_c;

    float acc1 = 0.0f;
    float acc2 = 0.0f;

    const int nchunks = (N + 31) >> 5;
    for (int c = part; c < nchunks; c += SPLIT_J) {
        const int j = (c << 5) + lane;

        float w = 0.0f;
        float d = 0.0f;
        if (j < N) {
            const float dx = xi - coords[3 * j + 0] * inv_c;
            const float dy = yi - coords[3 * j + 1] * inv_c;
            const float dz = zi - coords[3 * j + 2] * inv_c;
            const float sq = fmaf(dx, dx, fmaf(dy, dy, dz * dz));
            if (sq <= 1.0f) {
                d = sqrtf(fmaxf(sq, 1e-12f));
                w = __cosf(PI_HALF * d) * f[j];
            }
        }

        // compact over active lanes: broadcast (d, w) of each active j,
        // every lane contributes its 2 owned basis taps.
        unsigned bits = __ballot_sync(0xffffffffu, w != 0.0f);
        while (bits) {
            const int k = __ffs(bits) - 1;
            bits &= bits - 1;
            const float dk = __shfl_sync(0xffffffffu, d, k);
            const float wk = __shfl_sync(0xffffffffu, w, k);

            const float t1 = dk - m1;
            const float t2 = dk - m2;
            // exp underflows to 0 for far-away basis indices == reference tail
            acc1 = fmaf(wk, __expf(-beta * t1 * t1), acc1);
            acc2 = fmaf(wk, __expf(-beta * t2 * t2), acc2);
        }
    }

    // combine SPLIT_J partial rows (16K total global atomics — negligible)
    atomicAdd(&out[i * NBASIS + lane],      acc1);
    atomicAdd(&out[i * NBASIS + lane + 32], acc2);
}

extern "C" void kernel_launch(void* const* d_in, const int* in_sizes, int n_in,
                              void* d_out, int out_size) {
    const float* f      = (const float*)d_in[0];
    const float* coords = (const float*)d_in[1];
    const float* means  = (const float*)d_in[2];
    const float* beta   = (const float*)d_in[3];
    float* out          = (float*)d_out;

    const int N = in_sizes[0];          // 2048

    // zero the (poisoned) output, then accumulate
    {
        int threads = 256;
        int blocks  = (out_size + threads - 1) / threads;
        wgp_zero_kernel<<<blocks, threads>>>(out, out_size);
    }
    {
        const int warps_total = N * SPLIT_J;
        const int threads     = 256;                      // 8 warps/block
        const int blocks      = (warps_total * 32 + threads - 1) / threads;
        wgp_main_kernel<<<blocks, threads>>>(f, coords, means, beta, out, N);
    }
}

// round 2
// speedup vs baseline: 1.5870x; 1.5870x over previous
#include <cuda_runtime.h>
#include <math.h>

// WeightedGaussianPool: O[i,b] = sum_j cos(pi/2*d_ij) * step(1-d_ij) * f_j
//                                      * exp(-beta*(d_ij - means[b])^2)
// N=2048, B=64, beta=4096, means = linspace(0,1,64).
//
// Round-2 structure:
//  - warp owns (row i, j-partition); lane l owns bases l and l+32.
//  - per 32-j chunk: compute (d, W=cos*f) SIMD, compact active pairs into
//    shared {d,W} via ballot/popc, then counter-loop with LDS.64 broadcast.
//  - KEY: bases l and l+32 are 32/63 apart; exp(-4096*(>=16/63)^2) == 0,
//    so at most ONE tap per (pair,lane) is nonzero -> single EX2 per pair,
//    routed by predicate (d < midpoint). Bit-identical to the 2-exp version.

#define CUTOFF   5.0f
#define PI_HALF  1.5707963267948966f
#define NBASIS   64
#define SPLIT_J  4
#define WPB      4      // warps per block

__global__ void wgp_zero_kernel(float* __restrict__ out, int n) {
    int idx = blockIdx.x * blockDim.x + threadIdx.x;
    if (idx < n) out[idx] = 0.0f;
}

__global__ __launch_bounds__(WPB * 32)
void wgp_main_kernel(const float* __restrict__ f,
                     const float* __restrict__ coords,
                     const float* __restrict__ means,
                     const float* __restrict__ beta_p,
                     float* __restrict__ out,
                     int N) {
    __shared__ float2 buf[WPB][32];

    const int lane = threadIdx.x & 31;
    const int wrp  = threadIdx.x >> 5;
    const int gw   = blockIdx.x * WPB + wrp;
    const int i    = gw / SPLIT_J;
    const int part = gw % SPLIT_J;
    if (i >= N) return;

    const float beta = *beta_p;
    const float K2   = -beta * 1.4426950408889634f;   // -beta*log2(e)
    const float m1   = means[lane];
    const float m2   = means[lane + 32];
    const float mid  = 0.5f * (m1 + m2);
    const float inv_c2 = 1.0f / (CUTOFF * CUTOFF);

    const float xi = coords[3 * i + 0];
    const float yi = coords[3 * i + 1];
    const float zi = coords[3 * i + 2];

    float acc1 = 0.0f, acc2 = 0.0f;

    const int nchunks = (N + 31) >> 5;
    for (int c = part; c < nchunks; c += SPLIT_J) {
        const int j = (c << 5) + lane;

        float d = 0.0f, w = 0.0f;
        bool act = false;
        if (j < N) {
            const float dx = xi - coords[3 * j + 0];
            const float dy = yi - coords[3 * j + 1];
            const float dz = zi - coords[3 * j + 2];
            const float sq = fmaf(dx, dx, fmaf(dy, dy, dz * dz)) * inv_c2;
            if (sq <= 1.0f) {
                act = true;
                d = sqrtf(fmaxf(sq, 1e-12f));
                w = __cosf(PI_HALF * d) * f[j];
            }
        }

        const unsigned bits = __ballot_sync(0xffffffffu, act);
        if (!bits) continue;

        // compact active (d, W) pairs into shared
        const int pos = __popc(bits & ((1u << lane) - 1));
        if (act) buf[wrp][pos] = make_float2(d, w);
        __syncwarp();

        const int nact = __popc(bits);
        #pragma unroll 4
        for (int k = 0; k < nact; ++k) {
            const float2 p = buf[wrp][k];           // LDS.64 broadcast
            const bool  lo = p.x < mid;             // which tap can be nonzero
            const float m  = lo ? m1 : m2;
            const float t  = p.x - m;
            const float e  = exp2f(K2 * t * t);     // single EX2 per pair
            const float v  = p.y * e;
            if (lo) acc1 += v; else acc2 += v;      // predicated adds
        }
        __syncwarp();
    }

    atomicAdd(&out[i * NBASIS + lane],      acc1);
    atomicAdd(&out[i * NBASIS + lane + 32], acc2);
}

extern "C" void kernel_launch(void* const* d_in, const int* in_sizes, int n_in,
                              void* d_out, int out_size) {
    const float* f      = (const float*)d_in[0];
    const float* coords = (const float*)d_in[1];
    const float* means  = (const float*)d_in[2];
    const float* beta   = (const float*)d_in[3];
    float* out          = (float*)d_out;

    const int N = in_sizes[0];   // 2048

    {
        int threads = 256;
        int blocks  = (out_size + threads - 1) / threads;
        wgp_zero_kernel<<<blocks, threads>>>(out, out_size);
    }
    {
        const int warps_total = N * SPLIT_J;                 // 8192
        const int blocks      = (warps_total + WPB - 1) / WPB;
        wgp_main_kernel<<<blocks, WPB * 32>>>(f, coords, means, beta, out, N);
    }
}

// round 3
// speedup vs baseline: 1.7787x; 1.1208x over previous
#include <cuda_runtime.h>
#include <math.h>

// WeightedGaussianPool: O[i,b] = sum_j cos(pi/2*d_ij)*step(1-d_ij)*f_j
//                                      * exp(-beta*(d_ij-means[b])^2)
// N=2048, B=64, beta=4096, means=linspace(0,1,64).
//
// R3 structure:
//  - prep kernel: zero output + transpose coords to SoA, pre-normalized by 1/C.
//  - warp owns (row i, j-partition); lane l owns bases l and l+32.
//    Bases 32/63 apart => at most ONE tap nonzero per (pair,lane) =>
//    single EX2 routed by predicate (d < per-lane midpoint).
//  - distances pre-scaled by a=sqrt(beta*log2(e)) so consumer is
//    t = d' - a*m; e = ex2(-t*t)  (negation free in FMUL).
//  - compacted pair list padded to x4; inner loop = 2x LDS.128, 4 pairs/iter.

#define CUTOFF   5.0f
#define PI_HALF  1.5707963267948966f
#define NBASIS   64
#define SPLIT_J  8
#define WPB      8
#define NMAX     4096

__device__ float g_xs[NMAX];
__device__ float g_ys[NMAX];
__device__ float g_zs[NMAX];

__global__ void wgp_prep_kernel(const float* __restrict__ coords,
                                float* __restrict__ out,
                                int N, int out_n) {
    int idx = blockIdx.x * blockDim.x + threadIdx.x;
    if (idx < out_n) out[idx] = 0.0f;
    if (idx < N) {
        const float inv_c = 1.0f / CUTOFF;
        g_xs[idx] = coords[3 * idx + 0] * inv_c;
        g_ys[idx] = coords[3 * idx + 1] * inv_c;
        g_zs[idx] = coords[3 * idx + 2] * inv_c;
    }
}

__device__ __forceinline__ float ex2_fast(float x) {
    float r;
    asm("ex2.approx.ftz.f32 %0, %1;" : "=f"(r) : "f"(x));
    return r;
}

__global__ __launch_bounds__(WPB * 32)
void wgp_main_kernel(const float* __restrict__ f,
                     const float* __restrict__ means,
                     const float* __restrict__ beta_p,
                     float* __restrict__ out,
                     int N) {
    __shared__ __align__(16) float2 buf[WPB][36];

    const int lane = threadIdx.x & 31;
    const int wrp  = threadIdx.x >> 5;
    const int gw   = blockIdx.x * WPB + wrp;
    const int i    = gw / SPLIT_J;
    const int part = gw % SPLIT_J;
    if (i >= N) return;

    const float beta = *beta_p;
    const float a    = sqrtf(beta * 1.4426950408889634f); // sqrt(beta*log2 e)
    const float am1  = a * means[lane];
    const float am2  = a * means[lane + 32];
    const float midp = 0.5f * (am1 + am2);

    const float xi = g_xs[i];
    const float yi = g_ys[i];
    const float zi = g_zs[i];

    float acc1 = 0.0f, acc2 = 0.0f;

    const int nchunks = (N + 31) >> 5;
    for (int c = part; c < nchunks; c += SPLIT_J) {
        const int j = (c << 5) + lane;

        float dp = 0.0f, w = 0.0f;
        bool act = false;
        if (j < N) {
            const float dx = xi - g_xs[j];
            const float dy = yi - g_ys[j];
            const float dz = zi - g_zs[j];
            const float sq = fmaf(dx, dx, fmaf(dy, dy, dz * dz));
            if (sq <= 1.0f) {
                act = true;
                const float dn = sqrtf(fmaxf(sq, 1e-12f));
                dp = a * dn;                       // pre-scaled distance
                w  = __cosf(PI_HALF * dn) * f[j];
            }
        }

        const unsigned bits = __ballot_sync(0xffffffffu, act);
        if (!bits) continue;

        const int pos  = __popc(bits & ((1u << lane) - 1));
        const int nact = __popc(bits);
        if (act) buf[wrp][pos] = make_float2(dp, w);
        if (lane < 3) buf[wrp][nact + lane] = make_float2(1.0e4f, 0.0f); // pad
        __syncwarp();

        const int n4 = (nact + 3) & ~3;

#define PAIR(dq, wq)                                            \
        {                                                       \
            const bool  lo = (dq) < midp;                       \
            const float mm = lo ? am1 : am2;                    \
            const float t  = (dq) - mm;                         \
            const float e  = ex2_fast(-t * t);                  \
            const float v  = (wq) * e;                          \
            if (lo) acc1 += v; else acc2 += v;                  \
        }

        for (int k = 0; k < n4; k += 4) {
            const float4 q0 = *(const float4*)&buf[wrp][k];     // d0,w0,d1,w1
            const float4 q1 = *(const float4*)&buf[wrp][k + 2]; // d2,w2,d3,w3
            PAIR(q0.x, q0.y)
            PAIR(q0.z, q0.w)
            PAIR(q1.x, q1.y)
            PAIR(q1.z, q1.w)
        }
#undef PAIR
        __syncwarp();
    }

    atomicAdd(&out[i * NBASIS + lane],      acc1);
    atomicAdd(&out[i * NBASIS + lane + 32], acc2);
}

extern "C" void kernel_launch(void* const* d_in, const int* in_sizes, int n_in,
                              void* d_out, int out_size) {
    const float* f      = (const float*)d_in[0];
    const float* coords = (const float*)d_in[1];
    const float* means  = (const float*)d_in[2];
    const float* beta   = (const float*)d_in[3];
    float* out          = (float*)d_out;

    const int N = in_sizes[0];   // 2048

    {
        int threads = 256;
        int blocks  = (out_size + threads - 1) / threads;
        wgp_prep_kernel<<<blocks, threads>>>(coords, out, N, out_size);
    }
    {
        const int warps_total = N * SPLIT_J;                    // 16384
        const int blocks      = (warps_total + WPB - 1) / WPB;  // 2048
        wgp_main_kernel<<<blocks, WPB * 32>>>(f, means, beta, out, N);
    }
}

// round 4
// speedup vs baseline: 1.7823x; 1.0020x over previous
#include <cuda_runtime.h>
#include <math.h>

// WeightedGaussianPool: O[i,b] = sum_j cos(pi/2*d_ij)*step(1-d_ij)*f_j
//                                      * exp(-beta*(d_ij-means[b])^2)
// N=2048, B=64, beta=4096, means=linspace(0,1,64).
//
// R4 structure:
//  - prep kernel: coords -> SoA, pre-normalized by 1/CUTOFF.
//  - block == row i; its 8 warps each own a j-partition. Lane l owns bases
//    l and l+32 (32/63 apart => at most ONE Gaussian tap nonzero per pair
//    per lane => single EX2, routed by predicate).
//  - distances pre-scaled by a=sqrt(beta*log2 e): e = ex2(-t*t).
//  - compacted active-pair list in smem, x4-unrolled LDS.128 consumer,
//    predicated FFMA accumulate (no v-mul, no atomics).
//  - block-level smem reduction, one plain STG per output element.

#define CUTOFF   5.0f
#define PI_HALF  1.5707963267948966f
#define NBASIS   64
#define SPLIT_J  8
#define WPB      8
#define NMAX     4096

__device__ float g_xs[NMAX];
__device__ float g_ys[NMAX];
__device__ float g_zs[NMAX];

__global__ void wgp_prep_kernel(const float* __restrict__ coords, int N) {
    int idx = blockIdx.x * blockDim.x + threadIdx.x;
    if (idx < N) {
        const float inv_c = 1.0f / CUTOFF;
        g_xs[idx] = coords[3 * idx + 0] * inv_c;
        g_ys[idx] = coords[3 * idx + 1] * inv_c;
        g_zs[idx] = coords[3 * idx + 2] * inv_c;
    }
}

__device__ __forceinline__ float ex2_fast(float x) {
    float r;
    asm("ex2.approx.ftz.f32 %0, %1;" : "=f"(r) : "f"(x));
    return r;
}

__global__ __launch_bounds__(WPB * 32)
void wgp_main_kernel(const float* __restrict__ f,
                     const float* __restrict__ means,
                     const float* __restrict__ beta_p,
                     float* __restrict__ out,
                     int N) {
    __shared__ __align__(16) float2 buf[WPB][36];
    __shared__ float red[WPB][NBASIS];

    const int lane = threadIdx.x & 31;
    const int wrp  = threadIdx.x >> 5;
    const int i    = blockIdx.x;           // row
    const int part = wrp;                  // j-partition (WPB == SPLIT_J)
    if (i >= N) return;

    const float beta = *beta_p;
    const float a    = sqrtf(beta * 1.4426950408889634f); // sqrt(beta*log2 e)
    const float am1  = a * means[lane];
    const float am2  = a * means[lane + 32];
    const float D    = am2 - am1;                          // warp-uniform
    const float midp = 0.5f * (am1 + am2);

    const float xi = g_xs[i];
    const float yi = g_ys[i];
    const float zi = g_zs[i];

    float acc1 = 0.0f, acc2 = 0.0f;

    const int nchunks = (N + 31) >> 5;
    for (int c = part; c < nchunks; c += SPLIT_J) {
        const int j = (c << 5) + lane;

        float dp = 0.0f, w = 0.0f;
        bool act = false;
        if (j < N) {
            const float dx = xi - g_xs[j];
            const float dy = yi - g_ys[j];
            const float dz = zi - g_zs[j];
            const float sq = fmaf(dx, dx, fmaf(dy, dy, dz * dz));
            if (sq <= 1.0f) {
                act = true;
                const float dn = sqrtf(fmaxf(sq, 1e-12f));
                dp = a * dn;                        // pre-scaled distance
                w  = __cosf(PI_HALF * dn) * f[j];
            }
        }

        const unsigned bits = __ballot_sync(0xffffffffu, act);
        if (!bits) continue;

        const int pos  = __popc(bits & ((1u << lane) - 1));
        const int nact = __popc(bits);
        if (act) buf[wrp][pos] = make_float2(dp, w);
        if (lane < 3) buf[wrp][nact + lane] = make_float2(1.0e4f, 0.0f); // pad
        __syncwarp();

        const int n4 = (nact + 3) & ~3;

#define PAIR(dq, wq)                                              \
        {                                                         \
            const float t1 = (dq) - am1;                          \
            const bool  lo = (dq) < midp;                         \
            const float t  = lo ? t1 : (t1 - D);                  \
            const float e  = ex2_fast(-t * t);                    \
            if (lo) acc1 = fmaf((wq), e, acc1);                   \
            else    acc2 = fmaf((wq), e, acc2);                   \
        }

        for (int k = 0; k < n4; k += 4) {
            const float4 q0 = *(const float4*)&buf[wrp][k];       // d0,w0,d1,w1
            const float4 q1 = *(const float4*)&buf[wrp][k + 2];   // d2,w2,d3,w3
            PAIR(q0.x, q0.y)
            PAIR(q0.z, q0.w)
            PAIR(q1.x, q1.y)
            PAIR(q1.z, q1.w)
        }
#undef PAIR
        __syncwarp();
    }

    // block-level reduction across the 8 partitions, one STG per element
    red[wrp][lane]      = acc1;
    red[wrp][lane + 32] = acc2;
    __syncthreads();

    const int tid = threadIdx.x;
    if (tid < NBASIS) {
        float s = 0.0f;
        #pragma unroll
        for (int r = 0; r < WPB; ++r) s += red[r][tid];
        out[i * NBASIS + tid] = s;
    }
}

extern "C" void kernel_launch(void* const* d_in, const int* in_sizes, int n_in,
                              void* d_out, int out_size) {
    const float* f      = (const float*)d_in[0];
    const float* coords = (const float*)d_in[1];
    const float* means  = (const float*)d_in[2];
    const float* beta   = (const float*)d_in[3];
    float* out          = (float*)d_out;

    const int N = in_sizes[0];   // 2048

    {
        int threads = 256;
        int blocks  = (N + threads - 1) / threads;
        wgp_prep_kernel<<<blocks, threads>>>(coords, N);
    }
    {
        wgp_main_kernel<<<N, WPB * 32>>>(f, means, beta, out, N);
    }
}